// round 16
// baseline (speedup 1.0000x reference)
#include <cuda_runtime.h>

// FeatureInteraction: B=16384, F=27, D=128
// out[b] = concat(embeddings[b].flatten() (3456), triu(E E^T, k=1) (351)) -> 3807 floats
//
// R16 (from R9 base): ALL output written through per-row shifted aligned
//      128B windows (shift = b mod 32, since 3807 = -1 mod 32) -> every STG
//      is a single-line wavefront (was 2 for all flat stores). Sources: staged
//      tile (de-swizzled, conflict-free LDS) for flat words, per-pair triu
//      scratch for gram words. Reduction: dh1 scatters partials directly into
//      triu scratch, dh0 accumulates in place (no 448-word deposit pass).
//      Staging: cp.async.cg direct to swizzled smem (pad row zfilled).

static constexpr int F      = 27;
static constexpr int F_PAD  = 28;
static constexpr int D      = 128;
static constexpr int FLAT   = F * D;              // 3456
static constexpr int NPAIR  = (F * (F - 1)) / 2;  // 351
static constexpr int ROWLEN = FLAT + NPAIR;       // 3807
static constexpr int SLOT   = F_PAD * D;          // 3584 words per batch tile
static constexpr int NBATCH = 2;                  // pairs per block
static constexpr int THREADS = 128;

__device__ __forceinline__ unsigned long long pack2(float x, float y) {
    unsigned long long r;
    asm("mov.b64 %0, {%1, %2};" : "=l"(r) : "f"(x), "f"(y));
    return r;
}
__device__ __forceinline__ void unpack2(unsigned long long v, float& x, float& y) {
    asm("mov.b64 {%0, %1}, %2;" : "=f"(x), "=f"(y) : "l"(v));
}
__device__ __forceinline__ void ffma2(unsigned long long& acc,
                                      unsigned long long a, unsigned long long b) {
    asm("fma.rn.f32x2 %0, %1, %2, %0;" : "+l"(acc) : "l"(a), "l"(b));
}
__device__ __forceinline__ void cp_async16(unsigned smem_addr, const void* gptr, int src_sz) {
    asm volatile("cp.async.cg.shared.global [%0], [%1], 16, %2;"
                 :: "r"(smem_addr), "l"(gptr), "r"(src_sz));
}

// Row f = words [f*128, f*128+128); 16B chunk c stored at slot c ^ (f>>2).
// The XOR permutes chunks within their 8-chunk octet (f>>2 <= 6), so d-half
// regions are closed under it, and 32 consecutive d stay bank-distinct.
__device__ __forceinline__ int sm_word(int f, int d) {
    return f * D + ((((d >> 2) ^ (f >> 2)) << 2) | (d & 3));
}

__global__ void __launch_bounds__(THREADS, 7)
fi_kernel(const float* __restrict__ in, float* __restrict__ out, int batch)
{
    __shared__ float sm[NBATCH * SLOT];           // 28672 B (tile per pair)
    __shared__ float scr[NBATCH][NPAIR + 33];     // 3072 B (triu scratch per pair)

    const int tid  = threadIdx.x;
    const int pair = tid >> 6;                    // 0,1: independent pairs
    const int dh   = (tid >> 5) & 1;              // d-half owned by this warp
    const int lane = tid & 31;
    const long b   = (long)blockIdx.x * NBATCH + pair;
    if (b >= batch) return;                       // whole pair exits together

    float* smb  = sm + pair * SLOT;
    float* scrp = scr[pair];
    const float* __restrict__ inb  = in  + (size_t)b * FLAT;
    float*       __restrict__ outb = out + (size_t)b * ROWLEN;

    // lane -> 4x4 tile coords of the 7x7 tile grid over the triangle
    int ti = 0, tj = 0;
    if (lane < 28) {
        int l = lane, cnt = 7;
        while (l >= cnt) { l -= cnt; ++ti; --cnt; }
        tj = ti + l;
    }

    // ---- Stage this warp's d-half: 14 cp.async.cg 16B per lane. lane group
    // g handles rows of parity g; pad row 27 zero-filled via src_size=0.
    {
        const int g  = lane >> 4;
        const int cq = (lane & 15) + dh * 16;     // chunk 0..31 within row
        const float4* g4 = reinterpret_cast<const float4*>(inb);
        #pragma unroll
        for (int k = 0; k < 14; ++k) {
            const int f = 2 * k + g;              // 0..27 (27 = pad)
            const unsigned sa = (unsigned)__cvta_generic_to_shared(
                smb + f * D + ((cq ^ (f >> 2)) << 2));
            cp_async16(sa, (f < F) ? (const void*)(g4 + f * 32 + cq) : (const void*)g4,
                       (f < F) ? 16 : 0);
        }
        asm volatile("cp.async.commit_group;" ::: "memory");
        asm volatile("cp.async.wait_group 0;" ::: "memory");
    }
    __syncwarp();

    // ---- Partial gram over this warp's chunks [16dh, 16dh+16) ----
    float val[4][4];
    if (lane < 28) {
        unsigned long long acc[4][4];
        #pragma unroll
        for (int r = 0; r < 4; ++r)
            #pragma unroll
            for (int c = 0; c < 4; ++c) acc[r][c] = 0ull;

        const float* pi = smb + (4 * ti) * D;
        const float* pj = smb + (4 * tj) * D;

        const int c0 = dh * 16;
        #pragma unroll 2
        for (int c = c0; c < c0 + 16; ++c) {
            const int ci = (c ^ ti) << 2;
            const int cj = (c ^ tj) << 2;
            float4 ai4[4], aj4[4];
            #pragma unroll
            for (int r = 0; r < 4; ++r)
                ai4[r] = *reinterpret_cast<const float4*>(pi + r * D + ci);
            #pragma unroll
            for (int cc = 0; cc < 4; ++cc)
                aj4[cc] = *reinterpret_cast<const float4*>(pj + cc * D + cj);

            unsigned long long ailo[4], aihi[4], ajlo[4], ajhi[4];
            #pragma unroll
            for (int r = 0; r < 4; ++r) {
                ailo[r] = pack2(ai4[r].x, ai4[r].y);
                aihi[r] = pack2(ai4[r].z, ai4[r].w);
            }
            #pragma unroll
            for (int cc = 0; cc < 4; ++cc) {
                ajlo[cc] = pack2(aj4[cc].x, aj4[cc].y);
                ajhi[cc] = pack2(aj4[cc].z, aj4[cc].w);
            }
            #pragma unroll
            for (int r = 0; r < 4; ++r)
                #pragma unroll
                for (int cc = 0; cc < 4; ++cc) {
                    ffma2(acc[r][cc], ailo[r], ajlo[cc]);
                    ffma2(acc[r][cc], aihi[r], ajhi[cc]);
                }
        }
        #pragma unroll
        for (int r = 0; r < 4; ++r)
            #pragma unroll
            for (int cc = 0; cc < 4; ++cc) {
                float lo, hi;
                unpack2(acc[r][cc], lo, hi);
                val[r][cc] = lo + hi;
            }
    }

    // ---- Reduction directly in triu scratch ----
    // dh1 scatters its partials; dh0 accumulates in place (each off owned by
    // exactly one (lane, v) in each warp).
    if (lane < 28 && dh == 1) {
        #pragma unroll
        for (int v = 0; v < 16; ++v) {
            const int ii = 4 * ti + (v >> 2), jj = 4 * tj + (v & 3);
            if (ii < jj && jj < F)
                scrp[ii * F - (ii * (ii + 1)) / 2 + (jj - ii - 1)] = val[v >> 2][v & 3];
        }
    }
    asm volatile("bar.sync %0, 64;" :: "r"(1 + pair) : "memory");  // bar A
    if (lane < 28 && dh == 0) {
        #pragma unroll
        for (int v = 0; v < 16; ++v) {
            const int ii = 4 * ti + (v >> 2), jj = 4 * tj + (v & 3);
            if (ii < jj && jj < F) {
                const int off = ii * F - (ii * (ii + 1)) / 2 + (jj - ii - 1);
                scrp[off] += val[v >> 2][v & 3];
            }
        }
    }
    asm volatile("bar.sync %0, 64;" :: "r"(1 + pair) : "memory");  // bar B

    // ---- Epilogue: whole row (flat + triu) through shifted aligned windows.
    // base word index = b*3807 === -b (mod 32)  =>  shift = b & 31 makes
    // outb + shift 128B-aligned; every full-line store is 1 wavefront.
    const int shift = (int)(b & 31);
    const int nfull = (ROWLEN - shift) >> 5;      // 118 full lines

    // head partial (words [0, shift)): pure flat, f=0, sm_word(0,d)=d
    if (dh == 0 && lane < shift)
        outb[lane] = smb[lane];

    for (int k = dh; k < nfull; k += 2) {         // interleave warps
        const int ob = shift + k * 32;            // line base (warp-uniform)
        const int o  = ob + lane;
        float v;
        if (ob + 32 <= FLAT) {                    // pure flat line
            v = smb[sm_word(o >> 7, o & 127)];
        } else if (ob >= FLAT) {                  // pure triu line
            v = scrp[o - FLAT];
        } else {                                  // the single straddle line
            const int to = (o < FLAT) ? o : FLAT - 1;
            const float a = smb[sm_word(to >> 7, to & 127)];
            const int so = (o >= FLAT) ? (o - FLAT) : 0;
            v = (o < FLAT) ? a : scrp[so];
        }
        outb[o] = v;
    }

    // tail partial (always in the triu region: ROWLEN-32 > FLAT)
    if (dh == 1) {
        const int o = shift + nfull * 32 + lane;
        if (o < ROWLEN) outb[o] = scrp[o - FLAT];
    }
}

extern "C" void kernel_launch(void* const* d_in, const int* in_sizes, int n_in,
                              void* d_out, int out_size)
{
    const float* in = (const float*)d_in[0];
    float* out = (float*)d_out;
    const int batch = in_sizes[0] / FLAT;            // 16384
    const int grid = (batch + NBATCH - 1) / NBATCH;  // 8192
    fi_kernel<<<grid, THREADS>>>(in, out, batch);
}

// round 17
// speedup vs baseline: 1.5650x; 1.5650x over previous
#include <cuda_runtime.h>
#include <cstdint>

// FeatureInteraction: B=16384, F=27, D=128
// out[b] = concat(embeddings[b].flatten() (3456), triu(E E^T, k=1) (351)) -> 3807 floats
//
// R17: tf32 tensor-core gram. Per warp: 32x32xK64 via mma.sync.m16n8k8
//      (64 HMMA). Symmetry => A-fragments == B-fragments per lane: only
//      64 LDS.32 per warp (vs 256+ LDS.128 crossbar phases with FFMA2) —
//      removes the dominant L1 consumer. Row-XOR swizzle
//      word(f,d)=f*128+((((d>>2)^(f&7))<<2)|(d&3)) makes every fragment
//      load AND staging STS conflict-free (fragment rows satisfy
//      f&7 == lane>>2). Staging/flat-store: R8's proven deep-MLP scalar
//      LDG + register-direct STG. Rows 27-31 are garbage and discarded.

static constexpr int F      = 27;
static constexpr int D      = 128;
static constexpr int FLAT   = F * D;              // 3456
static constexpr int NPAIR  = (F * (F - 1)) / 2;  // 351
static constexpr int ROWLEN = FLAT + NPAIR;       // 3807
static constexpr int SLOT   = 28 * D;             // 3584 words per batch tile
static constexpr int NBATCH = 3;                  // pairs per block
static constexpr int THREADS = 192;

__device__ __forceinline__ uint32_t to_tf32(float x) {
    uint32_t r;
    asm("cvt.rna.tf32.f32 %0, %1;" : "=r"(r) : "f"(x));
    return r;
}
__device__ __forceinline__ void mma8(float* c,
                                     uint32_t a0, uint32_t a1, uint32_t a2, uint32_t a3,
                                     uint32_t b0, uint32_t b1) {
    asm("mma.sync.aligned.m16n8k8.row.col.f32.tf32.tf32.f32 "
        "{%0,%1,%2,%3}, {%4,%5,%6,%7}, {%8,%9}, {%0,%1,%2,%3};"
        : "+f"(c[0]), "+f"(c[1]), "+f"(c[2]), "+f"(c[3])
        : "r"(a0), "r"(a1), "r"(a2), "r"(a3), "r"(b0), "r"(b1));
}

// Row f = words [f*128, f*128+128); 4-word chunk (d>>2) stored at slot
// (d>>2) ^ (f&7). XOR stays within each 16-chunk half (f&7 <= 7), so the
// d-half regions [0,64) / [64,128) are closed under the swizzle.
__device__ __forceinline__ int sm_word(int f, int d) {
    return f * D + ((((d >> 2) ^ (f & 7)) << 2) | (d & 3));
}

__global__ void __launch_bounds__(THREADS, 4)
fi_kernel(const float* __restrict__ in, float* __restrict__ out, int batch)
{
    // 3 slots + 512-word pad: fragment loads touch rows 28-31 of the last
    // slot (garbage, finite-or-NaN bits; those outputs are discarded).
    __shared__ float sm[NBATCH * SLOT + 512];     // 45056 B

    const int tid  = threadIdx.x;
    const int pr   = tid >> 6;                    // pair 0..2 (batch slot)
    const int dh   = (tid >> 5) & 1;              // d-half owned by this warp
    const int lane = tid & 31;
    const long b   = (long)blockIdx.x * NBATCH + pr;
    if (b >= batch) return;                       // whole pair exits together

    float* smb = sm + pr * SLOT;
    const float* __restrict__ inb  = in  + (size_t)b * FLAT;
    float*       __restrict__ outb = out + (size_t)b * ROWLEN;

    const int d0 = dh * 64 + lane;                // this lane's two columns

    // ---- Stage this warp's d-half: 2 rounds of 27 batched LDGs; flat
    // output stored straight from registers (no smem round trip).
    {
        float v[F];
        #pragma unroll
        for (int f = 0; f < F; ++f) v[f] = inb[f * D + d0];
        #pragma unroll
        for (int f = 0; f < F; ++f) {
            smb[sm_word(f, d0)] = v[f];
            outb[f * D + d0]    = v[f];
        }
        #pragma unroll
        for (int f = 0; f < F; ++f) v[f] = inb[f * D + d0 + 32];
        #pragma unroll
        for (int f = 0; f < F; ++f) {
            smb[sm_word(f, d0 + 32)] = v[f];
            outb[f * D + d0 + 32]    = v[f];
        }
    }
    __syncwarp();

    // ---- tf32 mma gram over this warp's K-half (d in [64dh, 64dh+64)) ----
    // Fragment rows are f = 8R + (lane>>2), R=0..3 -> f&7 == lane>>2 == c_l.
    // Element (f, d): addr = base_l + R*1024 + ((K ^ c_l)<<2), K = d>>2.
    // Per k-step load 8 regs fr[R][h] (h: K0 / K0+1); by symmetry they serve
    // as BOTH the A-fragments and the B-fragments of every tile.
    float acc[2][4][4];
    #pragma unroll
    for (int mi = 0; mi < 2; ++mi)
        #pragma unroll
        for (int ni = 0; ni < 4; ++ni)
            #pragma unroll
            for (int r = 0; r < 4; ++r) acc[mi][ni][r] = 0.f;

    const int c_l = lane >> 2;
    const float* bl = smb + c_l * D + (lane & 3);

    #pragma unroll
    for (int kt = 0; kt < 8; ++kt) {
        const int K0 = dh * 16 + 2 * kt;
        const int o0 = (K0 ^ c_l) << 2;           // K0 even -> o1 = o0 ^ 4
        const int o1 = o0 ^ 4;
        uint32_t fr[4][2];
        #pragma unroll
        for (int R = 0; R < 4; ++R) {
            fr[R][0] = to_tf32(bl[R * 1024 + o0]);
            fr[R][1] = to_tf32(bl[R * 1024 + o1]);
        }
        #pragma unroll
        for (int mi = 0; mi < 2; ++mi)
            #pragma unroll
            for (int ni = 0; ni < 4; ++ni)
                mma8(acc[mi][ni],
                     fr[2 * mi][0], fr[2 * mi + 1][0],
                     fr[2 * mi][1], fr[2 * mi + 1][1],
                     fr[ni][0], fr[ni][1]);
    }
    __syncwarp();   // this warp's smem reads done; its d-half = scratch

    // C fragment layout: value (mi,ni,r) is gram[i][j] with
    //   i = mi*16 + c_l + (r>=2 ? 8 : 0),  j = ni*8 + 2*(lane&3) + (r&1).

    // ---- dh==1 deposits its 32 partials into its dead half (rows 0..15,
    // word 64 + (idx&1)*32 + lane at row idx>>1) — conflict-free.
    if (dh == 1) {
        #pragma unroll
        for (int mi = 0; mi < 2; ++mi)
            #pragma unroll
            for (int ni = 0; ni < 4; ++ni)
                #pragma unroll
                for (int r = 0; r < 4; ++r) {
                    const int idx = (mi * 4 + ni) * 4 + r;
                    smb[(idx >> 1) * D + 64 + (idx & 1) * 32 + lane] = acc[mi][ni][r];
                }
    }
    // bar A: deposits visible to dh0 (pair-scope named barrier, ids 1..3)
    asm volatile("bar.sync %0, 64;" :: "r"(1 + pr) : "memory");

    // ---- dh==0 reduces + scatters triu into its own dead half (cols 0-63,
    // rows 0-5) ----
    if (dh == 0) {
        #pragma unroll
        for (int mi = 0; mi < 2; ++mi)
            #pragma unroll
            for (int ni = 0; ni < 4; ++ni)
                #pragma unroll
                for (int r = 0; r < 4; ++r) {
                    const int idx = (mi * 4 + ni) * 4 + r;
                    const float s = acc[mi][ni][r]
                                  + smb[(idx >> 1) * D + 64 + (idx & 1) * 32 + lane];
                    const int i = mi * 16 + c_l + ((r >= 2) ? 8 : 0);
                    const int j = ni * 8 + 2 * (lane & 3) + (r & 1);
                    if (i < j && j < F) {
                        const int off = i * F - (i * (i + 1)) / 2 + (j - i - 1);
                        smb[(off >> 6) * D + (off & 63)] = s;
                    }
                }
        __syncwarp();
        // coalesced triu store
        float* outp = outb + FLAT;
        #pragma unroll
        for (int it = 0; it < (NPAIR + 31) / 32; ++it) {
            const int x = it * 32 + lane;
            if (x < NPAIR) outp[x] = smb[(x >> 6) * D + (x & 63)];
        }
    }
}

extern "C" void kernel_launch(void* const* d_in, const int* in_sizes, int n_in,
                              void* d_out, int out_size)
{
    const float* in = (const float*)d_in[0];
    float* out = (float*)d_out;
    const int batch = in_sizes[0] / FLAT;            // 16384
    const int grid = (batch + NBATCH - 1) / NBATCH;  // 5462
    fi_kernel<<<grid, THREADS>>>(in, out, batch);
}